// round 3
// baseline (speedup 1.0000x reference)
#include <cuda_runtime.h>
#include <cstdint>

#define NN 200000
#define NE 800000
#define HID 256

// ---------------- device scratch (no allocations allowed) ----------------
__device__ float g_buf0[(size_t)NN * HID];
__device__ float g_buf1[(size_t)NN * HID];
__device__ float g_agg [(size_t)NN * HID];
__device__ float g_weak[NN * 4];
__device__ float g_conf[NN];
__device__ float g_p3  [NN * 4];

// vectorized global reduction: dst[0..3] += v
__device__ __forceinline__ void red_add_v4(float* dst, float4 v)
{
    asm volatile("red.global.add.v4.f32 [%0], {%1, %2, %3, %4};"
                 :: "l"(dst), "f"(v.x), "f"(v.y), "f"(v.z), "f"(v.w)
                 : "memory");
}

// ---------------- node preprocessing: weak expert + conf + stage-1 of h --
// warp per node
__global__ void node_pre_kernel(const float* __restrict__ x,
                                const float* __restrict__ w1, const float* __restrict__ b1,
                                const float* __restrict__ w2, const float* __restrict__ b2,
                                const float* __restrict__ e1, const float* __restrict__ be1)
{
    int warp = (blockIdx.x * blockDim.x + threadIdx.x) >> 5;
    int lane = threadIdx.x & 31;
    if (warp >= NN) return;

    float xs[6];
#pragma unroll
    for (int i = 0; i < 6; i++) xs[i] = __ldg(&x[warp * 10 + 4 + i]);

    float pc0 = 0.f, pc1 = 0.f, pc2 = 0.f, pc3 = 0.f;
#pragma unroll
    for (int j = 0; j < 8; j++) {
        int t = lane + 32 * j;
        float ge = __ldg(&be1[t]);
        float gw = __ldg(&b1[t]);
#pragma unroll
        for (int i = 0; i < 6; i++) {
            ge = fmaf(xs[i], __ldg(&e1[i * HID + t]), ge);
            gw = fmaf(xs[i], __ldg(&w1[i * HID + t]), gw);
        }
        ge = fmaxf(ge, 0.f);
        gw = fmaxf(gw, 0.f);
        g_buf0[(size_t)warp * HID + t] = ge;
        pc0 = fmaf(gw, __ldg(&w2[t * 4 + 0]), pc0);
        pc1 = fmaf(gw, __ldg(&w2[t * 4 + 1]), pc1);
        pc2 = fmaf(gw, __ldg(&w2[t * 4 + 2]), pc2);
        pc3 = fmaf(gw, __ldg(&w2[t * 4 + 3]), pc3);
    }
#pragma unroll
    for (int o = 16; o > 0; o >>= 1) {
        pc0 += __shfl_xor_sync(0xffffffffu, pc0, o);
        pc1 += __shfl_xor_sync(0xffffffffu, pc1, o);
        pc2 += __shfl_xor_sync(0xffffffffu, pc2, o);
        pc3 += __shfl_xor_sync(0xffffffffu, pc3, o);
    }
    if (lane == 0) {
        float wk[4];
        wk[0] = pc0 + __ldg(&b2[0]);
        wk[1] = pc1 + __ldg(&b2[1]);
        wk[2] = pc2 + __ldg(&b2[2]);
        wk[3] = pc3 + __ldg(&b2[3]);
        float m = fmaxf(fmaxf(wk[0], wk[1]), fmaxf(wk[2], wk[3]));
        float ex[4], s = 0.f;
#pragma unroll
        for (int c = 0; c < 4; c++) { ex[c] = expf(wk[c] - m); s += ex[c]; }
        float inv = 1.f / s;
        float p[4], mean = 0.f;
#pragma unroll
        for (int c = 0; c < 4; c++) { p[c] = ex[c] * inv; mean += p[c]; }
        mean *= 0.25f;
        float var = 0.f, ent = 0.f;
#pragma unroll
        for (int c = 0; c < 4; c++) {
            float d = p[c] - mean;
            var += d * d;
            ent -= p[c] * logf(p[c] + 1e-8f);
        }
        var *= 0.25f;
        ent *= (1.f / 1.3862943611198906f);  // / log(4)
        float conf = 0.5f * (var + (1.f - ent));
        conf = fminf(fmaxf(conf, 0.f), 1.f);
        g_conf[warp] = conf;
#pragma unroll
        for (int c = 0; c < 4; c++) g_weak[warp * 4 + c] = wk[c];
    }
}

// ---------------- zero kernel (float4) ----------------
__global__ void zero_kernel(float4* __restrict__ p, int n4)
{
    int i = blockIdx.x * blockDim.x + threadIdx.x;
    if (i < n4) p[i] = make_float4(0.f, 0.f, 0.f, 0.f);
}

// ---------------- edge scatter: agg[tgt] += h[src], 256-wide ----------------
// 32 threads per edge, each handles 8 contiguous floats (2x float4 red.v4)
__global__ void scatter_kernel(const float* __restrict__ h, float* __restrict__ agg,
                               const int* __restrict__ src,
                               const int* __restrict__ tgt)
{
    int idx = blockIdx.x * blockDim.x + threadIdx.x;  // NE*32 threads
    if (idx >= NE * 32) return;
    int e = idx >> 5;
    int c = (idx & 31) << 3;   // 8 floats per thread
    int s = __ldg(&src[e]);
    int t = __ldg(&tgt[e]);
    const float4* hp = (const float4*)(h + (size_t)s * HID + c);
    float4 v0 = __ldg(hp);
    float4 v1 = __ldg(hp + 1);
    float* dst = agg + (size_t)t * HID + c;
    red_add_v4(dst, v0);
    red_add_v4(dst + 4, v1);
}

// ---------------- SGEMM: C[M,256] = act(A1@B1 (+ A2@B2) + bias) ----------------
// BM=128, BN=64, BK=16, 256 threads, 8x4 per thread
#define BM 128
#define BN 64
#define BK 16
__global__ __launch_bounds__(256) void gemm_kernel(
    const float* __restrict__ A1, const float* __restrict__ B1,
    const float* __restrict__ A2, const float* __restrict__ B2,
    const float* __restrict__ bias, float* __restrict__ C,
    int relu, int dual)
{
    __shared__ float As[BK][BM];
    __shared__ float Bs[BK][BN];
    const int tid = threadIdx.x;
    const int tx = tid & 15;   // N dir (4 cols each)
    const int ty = tid >> 4;   // M dir (8 rows each)
    const int bm = blockIdx.x * BM;
    const int bn = blockIdx.y * BN;

    float acc[8][4];
#pragma unroll
    for (int i = 0; i < 8; i++)
#pragma unroll
        for (int j = 0; j < 4; j++) acc[i][j] = 0.f;

    const int nPass = dual ? 2 : 1;
    for (int pass = 0; pass < nPass; ++pass) {
        const float* A = pass ? A2 : A1;
        const float* B = pass ? B2 : B1;
        for (int k0 = 0; k0 < 256; k0 += BK) {
            __syncthreads();
            // A tile: 128x16 = 512 float4, 2 per thread; stored transposed
#pragma unroll
            for (int l = 0; l < 2; l++) {
                int idx = tid + l * 256;   // 0..511
                int row = idx >> 2;        // 0..127
                int kq  = idx & 3;         // 0..3
                int grow = bm + row;
                float4 v = make_float4(0.f, 0.f, 0.f, 0.f);
                if (grow < NN)
                    v = *(const float4*)(A + (size_t)grow * 256 + k0 + kq * 4);
                As[kq * 4 + 0][row] = v.x;
                As[kq * 4 + 1][row] = v.y;
                As[kq * 4 + 2][row] = v.z;
                As[kq * 4 + 3][row] = v.w;
            }
            // B tile: 16x64 = 256 float4, 1 per thread
            {
                int k  = tid >> 4;
                int n4 = tid & 15;
                float4 v = *(const float4*)(B + (size_t)(k0 + k) * 256 + bn + n4 * 4);
                *(float4*)&Bs[k][n4 * 4] = v;
            }
            __syncthreads();
#pragma unroll
            for (int k = 0; k < BK; k++) {
                float a[8], b[4];
                *(float4*)&a[0] = *(const float4*)&As[k][ty * 8];
                *(float4*)&a[4] = *(const float4*)&As[k][ty * 8 + 4];
                *(float4*)&b[0] = *(const float4*)&Bs[k][tx * 4];
#pragma unroll
                for (int i = 0; i < 8; i++)
#pragma unroll
                    for (int j = 0; j < 4; j++)
                        acc[i][j] = fmaf(a[i], b[j], acc[i][j]);
            }
        }
    }
    float bz[4];
    *(float4*)bz = *(const float4*)(bias + bn + tx * 4);
#pragma unroll
    for (int i = 0; i < 8; i++) {
        int grow = bm + ty * 8 + i;
        if (grow < NN) {
            float4 o;
            o.x = acc[i][0] + bz[0];
            o.y = acc[i][1] + bz[1];
            o.z = acc[i][2] + bz[2];
            o.w = acc[i][3] + bz[3];
            if (relu) {
                o.x = fmaxf(o.x, 0.f); o.y = fmaxf(o.y, 0.f);
                o.z = fmaxf(o.z, 0.f); o.w = fmaxf(o.w, 0.f);
            }
            *(float4*)(C + (size_t)grow * 256 + bn + tx * 4) = o;
        }
    }
}

// ---------------- last layer projections + output init ----------------
// warp per node: p3 = h@rw3 ; out = conf*weak + (1-conf)*(h@sw3 + rb3)
__global__ void node_post_kernel(const float* __restrict__ h,
                                 const float* __restrict__ rw3,
                                 const float* __restrict__ rb3,
                                 const float* __restrict__ sw3,
                                 float* __restrict__ out)
{
    int warp = (blockIdx.x * blockDim.x + threadIdx.x) >> 5;
    int lane = threadIdx.x & 31;
    if (warp >= NN) return;

    float pp[4] = {0.f, 0.f, 0.f, 0.f};
    float ss[4] = {0.f, 0.f, 0.f, 0.f};
#pragma unroll
    for (int j = 0; j < 8; j++) {
        int t = lane + 32 * j;
        float hv = h[(size_t)warp * HID + t];
#pragma unroll
        for (int c = 0; c < 4; c++) {
            pp[c] = fmaf(hv, __ldg(&rw3[t * 4 + c]), pp[c]);
            ss[c] = fmaf(hv, __ldg(&sw3[t * 4 + c]), ss[c]);
        }
    }
#pragma unroll
    for (int o = 16; o > 0; o >>= 1) {
#pragma unroll
        for (int c = 0; c < 4; c++) {
            pp[c] += __shfl_xor_sync(0xffffffffu, pp[c], o);
            ss[c] += __shfl_xor_sync(0xffffffffu, ss[c], o);
        }
    }
    if (lane == 0) {
        float cf = g_conf[warp];
        float om = 1.f - cf;
#pragma unroll
        for (int c = 0; c < 4; c++) {
            out[warp * 4 + c] = cf * g_weak[warp * 4 + c] + om * (ss[c] + __ldg(&rb3[c]));
            g_p3[warp * 4 + c] = pp[c];
        }
    }
}

// ---------------- final 4-wide edge scatter: out[tgt] += (1-conf[tgt]) * p3[src]
__global__ void edge3_kernel(const int* __restrict__ src,
                             const int* __restrict__ tgt,
                             float* __restrict__ out)
{
    int e = blockIdx.x * blockDim.x + threadIdx.x;
    if (e >= NE) return;
    int s = __ldg(&src[e]);
    int t = __ldg(&tgt[e]);
    float om = 1.f - g_conf[t];
    float4 p = *(const float4*)&g_p3[s * 4];
    p.x *= om; p.y *= om; p.z *= om; p.w *= om;
    red_add_v4(&out[t * 4], p);
}

// ---------------- host ----------------
extern "C" void kernel_launch(void* const* d_in, const int* in_sizes, int n_in,
                              void* d_out, int out_size)
{
    const float* x   = (const float*)d_in[0];
    const int* ei    = (const int*)d_in[1];   // edge_index is int32 (JAX x64 disabled)
    const float* w1  = (const float*)d_in[2];
    const float* b1  = (const float*)d_in[3];
    const float* w2  = (const float*)d_in[4];
    const float* b2  = (const float*)d_in[5];
    const float* e1  = (const float*)d_in[6];
    const float* be1 = (const float*)d_in[7];
    const float* e2  = (const float*)d_in[8];
    const float* be2 = (const float*)d_in[9];
    const float* RW[3] = {(const float*)d_in[10], (const float*)d_in[13], (const float*)d_in[16]};
    const float* RB[3] = {(const float*)d_in[11], (const float*)d_in[14], (const float*)d_in[17]};
    const float* SW[3] = {(const float*)d_in[12], (const float*)d_in[15], (const float*)d_in[18]};
    const float* rw3 = (const float*)d_in[19];
    const float* rb3 = (const float*)d_in[20];
    const float* sw3 = (const float*)d_in[21];
    float* out = (float*)d_out;

    float *buf0, *buf1, *agg;
    cudaGetSymbolAddress((void**)&buf0, g_buf0);
    cudaGetSymbolAddress((void**)&buf1, g_buf1);
    cudaGetSymbolAddress((void**)&agg,  g_agg);

    const int* src = ei;
    const int* tgt = ei + NE;

    // stage 1: per-node
    node_pre_kernel<<<(NN * 32 + 255) / 256, 256>>>(x, w1, b1, w2, b2, e1, be1);

    dim3 gg((NN + BM - 1) / BM, 256 / BN);
    // h = g @ e2 + be2
    gemm_kernel<<<gg, 256>>>(buf0, e2, nullptr, nullptr, be2, buf1, 0, 0);

    float* hcur = buf1;
    float* hnext = buf0;
    const int z4 = NN * (HID / 4);
    for (int l = 0; l < 3; l++) {
        zero_kernel<<<(z4 + 255) / 256, 256>>>((float4*)agg, z4);
        scatter_kernel<<<(NE * 32 + 255) / 256, 256>>>(hcur, agg, src, tgt);
        gemm_kernel<<<gg, 256>>>(agg, RW[l], hcur, SW[l], RB[l], hnext, 1, 1);
        float* tmp = hcur; hcur = hnext; hnext = tmp;
    }

    node_post_kernel<<<(NN * 32 + 255) / 256, 256>>>(hcur, rw3, rb3, sw3, out);
    edge3_kernel<<<(NE + 255) / 256, 256>>>(src, tgt, out);
}

// round 5
// speedup vs baseline: 1.8502x; 1.8502x over previous
// Resubmission of round-4 kernel (round-4 bench died to container infra, not kernel).
// TF32 tensor-core GEMM for the 7 node-level 256x256 GEMMs; exact fp32 elsewhere.
#include <cuda_runtime.h>
#include <cstdint>

#define NN 200000
#define NE 800000
#define HID 256

// ---------------- device scratch (no allocations allowed) ----------------
__device__ float g_buf0[(size_t)NN * HID];
__device__ float g_buf1[(size_t)NN * HID];
__device__ float g_agg [(size_t)NN * HID];
__device__ float g_weak[NN * 4];
__device__ float g_conf[NN];
__device__ float g_p3  [NN * 4];

// vectorized global reduction: dst[0..3] += v
__device__ __forceinline__ void red_add_v4(float* dst, float4 v)
{
    asm volatile("red.global.add.v4.f32 [%0], {%1, %2, %3, %4};"
                 :: "l"(dst), "f"(v.x), "f"(v.y), "f"(v.z), "f"(v.w)
                 : "memory");
}

__device__ __forceinline__ float f2tf32(float f)
{
    uint32_t r;
    asm("cvt.rna.tf32.f32 %0, %1;" : "=r"(r) : "f"(f));
    return __uint_as_float(r);
}

// ---------------- node preprocessing: weak expert + conf + stage-1 of h --
// warp per node
__global__ void node_pre_kernel(const float* __restrict__ x,
                                const float* __restrict__ w1, const float* __restrict__ b1,
                                const float* __restrict__ w2, const float* __restrict__ b2,
                                const float* __restrict__ e1, const float* __restrict__ be1)
{
    int warp = (blockIdx.x * blockDim.x + threadIdx.x) >> 5;
    int lane = threadIdx.x & 31;
    if (warp >= NN) return;

    float xs[6];
#pragma unroll
    for (int i = 0; i < 6; i++) xs[i] = __ldg(&x[warp * 10 + 4 + i]);

    float pc0 = 0.f, pc1 = 0.f, pc2 = 0.f, pc3 = 0.f;
#pragma unroll
    for (int j = 0; j < 8; j++) {
        int t = lane + 32 * j;
        float ge = __ldg(&be1[t]);
        float gw = __ldg(&b1[t]);
#pragma unroll
        for (int i = 0; i < 6; i++) {
            ge = fmaf(xs[i], __ldg(&e1[i * HID + t]), ge);
            gw = fmaf(xs[i], __ldg(&w1[i * HID + t]), gw);
        }
        ge = fmaxf(ge, 0.f);
        gw = fmaxf(gw, 0.f);
        g_buf0[(size_t)warp * HID + t] = ge;
        pc0 = fmaf(gw, __ldg(&w2[t * 4 + 0]), pc0);
        pc1 = fmaf(gw, __ldg(&w2[t * 4 + 1]), pc1);
        pc2 = fmaf(gw, __ldg(&w2[t * 4 + 2]), pc2);
        pc3 = fmaf(gw, __ldg(&w2[t * 4 + 3]), pc3);
    }
#pragma unroll
    for (int o = 16; o > 0; o >>= 1) {
        pc0 += __shfl_xor_sync(0xffffffffu, pc0, o);
        pc1 += __shfl_xor_sync(0xffffffffu, pc1, o);
        pc2 += __shfl_xor_sync(0xffffffffu, pc2, o);
        pc3 += __shfl_xor_sync(0xffffffffu, pc3, o);
    }
    if (lane == 0) {
        float wk[4];
        wk[0] = pc0 + __ldg(&b2[0]);
        wk[1] = pc1 + __ldg(&b2[1]);
        wk[2] = pc2 + __ldg(&b2[2]);
        wk[3] = pc3 + __ldg(&b2[3]);
        float m = fmaxf(fmaxf(wk[0], wk[1]), fmaxf(wk[2], wk[3]));
        float ex[4], s = 0.f;
#pragma unroll
        for (int c = 0; c < 4; c++) { ex[c] = expf(wk[c] - m); s += ex[c]; }
        float inv = 1.f / s;
        float p[4], mean = 0.f;
#pragma unroll
        for (int c = 0; c < 4; c++) { p[c] = ex[c] * inv; mean += p[c]; }
        mean *= 0.25f;
        float var = 0.f, ent = 0.f;
#pragma unroll
        for (int c = 0; c < 4; c++) {
            float d = p[c] - mean;
            var += d * d;
            ent -= p[c] * logf(p[c] + 1e-8f);
        }
        var *= 0.25f;
        ent *= (1.f / 1.3862943611198906f);  // / log(4)
        float conf = 0.5f * (var + (1.f - ent));
        conf = fminf(fmaxf(conf, 0.f), 1.f);
        g_conf[warp] = conf;
#pragma unroll
        for (int c = 0; c < 4; c++) g_weak[warp * 4 + c] = wk[c];
    }
}

// ---------------- zero kernel (float4) ----------------
__global__ void zero_kernel(float4* __restrict__ p, int n4)
{
    int i = blockIdx.x * blockDim.x + threadIdx.x;
    if (i < n4) p[i] = make_float4(0.f, 0.f, 0.f, 0.f);
}

// ---------------- edge scatter: agg[tgt] += h[src], 256-wide ----------------
__global__ void scatter_kernel(const float* __restrict__ h, float* __restrict__ agg,
                               const int* __restrict__ src,
                               const int* __restrict__ tgt)
{
    int idx = blockIdx.x * blockDim.x + threadIdx.x;  // NE*32 threads
    if (idx >= NE * 32) return;
    int e = idx >> 5;
    int c = (idx & 31) << 3;   // 8 floats per thread
    int s = __ldg(&src[e]);
    int t = __ldg(&tgt[e]);
    const float4* hp = (const float4*)(h + (size_t)s * HID + c);
    float4 v0 = __ldg(hp);
    float4 v1 = __ldg(hp + 1);
    float* dst = agg + (size_t)t * HID + c;
    red_add_v4(dst, v0);
    red_add_v4(dst + 4, v1);
}

// ---------------- TF32 tensor-core GEMM ----------------
// C[M,256] = act(A1@B1 (+ A2@B2) + bias)
// BM=128, BN=128, BK=32; 256 threads = 8 warps in 2(M)x4(N) grid;
// warp tile 64x32 = 4x4 mma.m16n8k8 tiles.
#define BM 128
#define BN 128
#define BK 32
__global__ __launch_bounds__(256, 2) void gemm_tc_kernel(
    const float* __restrict__ A1, const float* __restrict__ B1,
    const float* __restrict__ A2, const float* __restrict__ B2,
    const float* __restrict__ bias, float* __restrict__ C,
    int relu, int dual)
{
    __shared__ float As[BM][BK + 4];   // 128 x 36 (A-frag loads bank-conflict-free)
    __shared__ float Bs[BK][BN + 4];   // 32 x 132

    const int tid  = threadIdx.x;
    const int warp = tid >> 5;
    const int lane = tid & 31;
    const int wm = warp & 1;         // 0..1 (M)
    const int wn = warp >> 1;        // 0..3 (N)
    const int g  = lane >> 2;        // group id 0..7
    const int t  = lane & 3;         // thread-in-group 0..3
    const int bm = blockIdx.x * BM;
    const int bn = blockIdx.y * BN;

    float acc[4][4][4];
#pragma unroll
    for (int mt = 0; mt < 4; mt++)
#pragma unroll
        for (int nt = 0; nt < 4; nt++)
#pragma unroll
            for (int c = 0; c < 4; c++) acc[mt][nt][c] = 0.f;

    const int nPass = dual ? 2 : 1;
    for (int pass = 0; pass < nPass; ++pass) {
        const float* A = pass ? A2 : A1;
        const float* B = pass ? B2 : B1;
        for (int k0 = 0; k0 < 256; k0 += BK) {
            __syncthreads();
            // A tile: 128 rows x 32 cols = 1024 float4 loads (tf32-converted)
#pragma unroll
            for (int i = 0; i < 4; i++) {
                int idx = tid + i * 256;
                int row = idx >> 3;
                int c4  = (idx & 7) << 2;
                int grow = bm + row;
                float4 v = make_float4(0.f, 0.f, 0.f, 0.f);
                if (grow < NN)
                    v = *(const float4*)(A + (size_t)grow * 256 + k0 + c4);
                float4 w;
                w.x = f2tf32(v.x); w.y = f2tf32(v.y);
                w.z = f2tf32(v.z); w.w = f2tf32(v.w);
                *(float4*)&As[row][c4] = w;
            }
            // B tile: 32 rows x 128 cols = 1024 float4 loads
#pragma unroll
            for (int i = 0; i < 4; i++) {
                int idx = tid + i * 256;
                int row = idx >> 5;
                int c4  = (idx & 31) << 2;
                float4 v = *(const float4*)(B + (size_t)(k0 + row) * 256 + bn + c4);
                float4 w;
                w.x = f2tf32(v.x); w.y = f2tf32(v.y);
                w.z = f2tf32(v.z); w.w = f2tf32(v.w);
                *(float4*)&Bs[row][c4] = w;
            }
            __syncthreads();
#pragma unroll
            for (int kk = 0; kk < BK; kk += 8) {
                uint32_t af[4][4];
#pragma unroll
                for (int mt = 0; mt < 4; mt++) {
                    int r0 = wm * 64 + mt * 16 + g;
                    af[mt][0] = __float_as_uint(As[r0    ][kk + t    ]);
                    af[mt][1] = __float_as_uint(As[r0 + 8][kk + t    ]);
                    af[mt][2] = __float_as_uint(As[r0    ][kk + t + 4]);
                    af[mt][3] = __float_as_uint(As[r0 + 8][kk + t + 4]);
                }
#pragma unroll
                for (int nt = 0; nt < 4; nt++) {
                    int cc = wn * 32 + nt * 8 + g;
                    uint32_t b0 = __float_as_uint(Bs[kk + t    ][cc]);
                    uint32_t b1 = __float_as_uint(Bs[kk + t + 4][cc]);
#pragma unroll
                    for (int mt = 0; mt < 4; mt++) {
                        asm volatile(
                            "mma.sync.aligned.m16n8k8.row.col.f32.tf32.tf32.f32 "
                            "{%0,%1,%2,%3}, {%4,%5,%6,%7}, {%8,%9}, {%0,%1,%2,%3};"
                            : "+f"(acc[mt][nt][0]), "+f"(acc[mt][nt][1]),
                              "+f"(acc[mt][nt][2]), "+f"(acc[mt][nt][3])
                            : "r"(af[mt][0]), "r"(af[mt][1]),
                              "r"(af[mt][2]), "r"(af[mt][3]),
                              "r"(b0), "r"(b1));
                    }
                }
            }
        }
    }

    // epilogue: c0:(g,2t) c1:(g,2t+1) c2:(g+8,2t) c3:(g+8,2t+1)
#pragma unroll
    for (int nt = 0; nt < 4; nt++) {
        int col = bn + wn * 32 + nt * 8 + 2 * t;
        float bz0 = __ldg(&bias[col]);
        float bz1 = __ldg(&bias[col + 1]);
#pragma unroll
        for (int mt = 0; mt < 4; mt++) {
            int row0 = bm + wm * 64 + mt * 16 + g;
            float v0 = acc[mt][nt][0] + bz0;
            float v1 = acc[mt][nt][1] + bz1;
            float v2 = acc[mt][nt][2] + bz0;
            float v3 = acc[mt][nt][3] + bz1;
            if (relu) {
                v0 = fmaxf(v0, 0.f); v1 = fmaxf(v1, 0.f);
                v2 = fmaxf(v2, 0.f); v3 = fmaxf(v3, 0.f);
            }
            if (row0 < NN)
                *(float2*)(C + (size_t)row0 * 256 + col) = make_float2(v0, v1);
            if (row0 + 8 < NN)
                *(float2*)(C + (size_t)(row0 + 8) * 256 + col) = make_float2(v2, v3);
        }
    }
}

// ---------------- last layer projections + output init (exact fp32) ----
__global__ void node_post_kernel(const float* __restrict__ h,
                                 const float* __restrict__ rw3,
                                 const float* __restrict__ rb3,
                                 const float* __restrict__ sw3,
                                 float* __restrict__ out)
{
    int warp = (blockIdx.x * blockDim.x + threadIdx.x) >> 5;
    int lane = threadIdx.x & 31;
    if (warp >= NN) return;

    float pp[4] = {0.f, 0.f, 0.f, 0.f};
    float ss[4] = {0.f, 0.f, 0.f, 0.f};
#pragma unroll
    for (int j = 0; j < 8; j++) {
        int t = lane + 32 * j;
        float hv = h[(size_t)warp * HID + t];
#pragma unroll
        for (int c = 0; c < 4; c++) {
            pp[c] = fmaf(hv, __ldg(&rw3[t * 4 + c]), pp[c]);
            ss[c] = fmaf(hv, __ldg(&sw3[t * 4 + c]), ss[c]);
        }
    }
#pragma unroll
    for (int o = 16; o > 0; o >>= 1) {
#pragma unroll
        for (int c = 0; c < 4; c++) {
            pp[c] += __shfl_xor_sync(0xffffffffu, pp[c], o);
            ss[c] += __shfl_xor_sync(0xffffffffu, ss[c], o);
        }
    }
    if (lane == 0) {
        float cf = g_conf[warp];
        float om = 1.f - cf;
#pragma unroll
        for (int c = 0; c < 4; c++) {
            out[warp * 4 + c] = cf * g_weak[warp * 4 + c] + om * (ss[c] + __ldg(&rb3[c]));
            g_p3[warp * 4 + c] = pp[c];
        }
    }
}

// ---------------- final 4-wide edge scatter ----------------
__global__ void edge3_kernel(const int* __restrict__ src,
                             const int* __restrict__ tgt,
                             float* __restrict__ out)
{
    int e = blockIdx.x * blockDim.x + threadIdx.x;
    if (e >= NE) return;
    int s = __ldg(&src[e]);
    int t = __ldg(&tgt[e]);
    float om = 1.f - g_conf[t];
    float4 p = *(const float4*)&g_p3[s * 4];
    p.x *= om; p.y *= om; p.z *= om; p.w *= om;
    red_add_v4(&out[t * 4], p);
}

// ---------------- host ----------------
extern "C" void kernel_launch(void* const* d_in, const int* in_sizes, int n_in,
                              void* d_out, int out_size)
{
    const float* x   = (const float*)d_in[0];
    const int* ei    = (const int*)d_in[1];   // edge_index is int32 (JAX x64 disabled)
    const float* w1  = (const float*)d_in[2];
    const float* b1  = (const float*)d_in[3];
    const float* w2  = (const float*)d_in[4];
    const float* b2  = (const float*)d_in[5];
    const float* e1  = (const float*)d_in[6];
    const float* be1 = (const float*)d_in[7];
    const float* e2  = (const float*)d_in[8];
    const float* be2 = (const float*)d_in[9];
    const float* RW[3] = {(const float*)d_in[10], (const float*)d_in[13], (const float*)d_in[16]};
    const float* RB[3] = {(const float*)d_in[11], (const float*)d_in[14], (const float*)d_in[17]};
    const float* SW[3] = {(const float*)d_in[12], (const float*)d_in[15], (const float*)d_in[18]};
    const float* rw3 = (const float*)d_in[19];
    const float* rb3 = (const float*)d_in[20];
    const float* sw3 = (const float*)d_in[21];
    float* out = (float*)d_out;

    float *buf0, *buf1, *agg;
    cudaGetSymbolAddress((void**)&buf0, g_buf0);
    cudaGetSymbolAddress((void**)&buf1, g_buf1);
    cudaGetSymbolAddress((void**)&agg,  g_agg);

    const int* src = ei;
    const int* tgt = ei + NE;

    node_pre_kernel<<<(NN * 32 + 255) / 256, 256>>>(x, w1, b1, w2, b2, e1, be1);

    dim3 gg((NN + BM - 1) / BM, 256 / BN);
    gemm_tc_kernel<<<gg, 256>>>(buf0, e2, nullptr, nullptr, be2, buf1, 0, 0);

    float* hcur = buf1;
    float* hnext = buf0;
    const int z4 = NN * (HID / 4);
    for (int l = 0; l < 3; l++) {
        zero_kernel<<<(z4 + 255) / 256, 256>>>((float4*)agg, z4);
        scatter_kernel<<<(NE * 32 + 255) / 256, 256>>>(hcur, agg, src, tgt);
        gemm_tc_kernel<<<gg, 256>>>(agg, RW[l], hcur, SW[l], RB[l], hnext, 1, 1);
        float* tmp = hcur; hcur = hnext; hnext = tmp;
    }

    node_post_kernel<<<(NN * 32 + 255) / 256, 256>>>(hcur, rw3, rb3, sw3, out);
    edge3_kernel<<<(NE + 255) / 256, 256>>>(src, tgt, out);
}